// round 11
// baseline (speedup 1.0000x reference)
#include <cuda_runtime.h>
#include <cuda_bf16.h>

typedef unsigned long long u64;
__device__ __forceinline__ u64 pk2(float lo, float hi) {
    u64 r; asm("mov.b64 %0, {%1, %2};" : "=l"(r) : "f"(lo), "f"(hi)); return r;
}
__device__ __forceinline__ void unpk2(u64 v, float& lo, float& hi) {
    asm("mov.b64 {%0, %1}, %2;" : "=f"(lo), "=f"(hi) : "l"(v));
}
__device__ __forceinline__ u64 mul2(u64 a, u64 b) {
    u64 r; asm("mul.rn.f32x2 %0, %1, %2;" : "=l"(r) : "l"(a), "l"(b)); return r;
}
__device__ __forceinline__ u64 fma2(u64 a, u64 b, u64 c) {
    u64 r; asm("fma.rn.f32x2 %0, %1, %2, %3;" : "=l"(r) : "l"(a), "l"(b), "l"(c)); return r;
}

// Coefficients in trig basis v = (1, cos x, sin x, cos 2x, sin 2x),
// packed u64 (both f32 lanes), rows padded to 6: layout [q][alpha][6].
__device__ u64 g_coef_v[120];
__device__ int g_flag = 0;

#define NBATCH_BLOCKS 592   // 148 SMs x 4 blocks/SM = exactly 1 wave

// ---------------------------------------------------------------------------
// Setup path (block 0 only), isolated via noinline.
// ---------------------------------------------------------------------------
__device__ __noinline__ void do_setup(const float* __restrict__ w, int tid) {
    __shared__ float2 wcs[36];
    __shared__ float2 S[16][16];
    __shared__ float  coefS[100];

    if (tid < 36) {
        float s, c; __sincosf(0.5f * w[tid], &s, &c);
        wcs[tid] = make_float2(c, s);
    }
    if (tid >= 64 && tid < 164) coefS[tid - 64] = 0.f;
    __syncthreads();

    // 16-lane group = one column of the 16x16 unitary
    {
        const int col = tid >> 4, k = tid & 15;
        float ar = (k == col) ? 1.f : 0.f, ai = 0.f;

        int sidx = k;                 // CNOT-ring inverse permutation
        if (sidx & 1) sidx ^= 8;
        if (sidx & 2) sidx ^= 1;
        if (sidx & 4) sidx ^= 2;
        if (sidx & 8) sidx ^= 4;

        #pragma unroll
        for (int l = 0; l < 3; l++) {
            #pragma unroll
            for (int q = 0; q < 4; q++) {
                const int pos = 3 - q, mask = 1 << pos;
                const int bit = (k >> pos) & 1;
                #pragma unroll
                for (int g = 0; g < 3; g++) {
                    const float2 cs = wcs[(l * 4 + q) * 3 + g];
                    const float c = cs.x, s = cs.y;
                    float nr, ni;
                    if (g == 2) {           // RZ
                        float t = bit ? -s : s;
                        nr = c * ar + t * ai;
                        ni = c * ai - t * ar;
                    } else {
                        float pr = __shfl_xor_sync(0xffffffffu, ar, mask);
                        float pi = __shfl_xor_sync(0xffffffffu, ai, mask);
                        if (g == 0) {       // RX
                            nr = c * ar + s * pi;
                            ni = c * ai - s * pr;
                        } else {            // RY
                            float t = bit ? s : -s;
                            nr = c * ar + t * pr;
                            ni = c * ai + t * pi;
                        }
                    }
                    ar = nr; ai = ni;
                }
            }
            ar = __shfl_sync(0xffffffffu, ar, sidx, 16);
            ai = __shfl_sync(0xffffffffu, ai, sidx, 16);
        }
        S[col][k] = make_float2(ar, ai);
    }
    __syncthreads();

    // A_q collapse -> 100 monomial coefficients (shared atomics)
    {
        const int i = tid >> 4, j = tid & 15;
        float s0 = 0.f, s1 = 0.f, s2 = 0.f, s3 = 0.f;
        #pragma unroll
        for (int k = 0; k < 16; k++) {
            float2 u = S[i][k], v = S[j][k];
            float p = u.x * v.x + u.y * v.y;
            s0 += ((k >> 3) & 1) ? -p : p;
            s1 += ((k >> 2) & 1) ? -p : p;
            s2 += ((k >> 1) & 1) ? -p : p;
            s3 += ( k       & 1) ? -p : p;
        }
        const int a_i = ((i >> 3) & 1) + ((i >> 1) & 1);
        const int b_i = ((i >> 2) & 1) + (i & 1);
        const int a_j = ((j >> 3) & 1) + ((j >> 1) & 1);
        const int b_j = ((j >> 2) & 1) + (j & 1);
        const int base = (a_i + a_j) * 5 + (b_i + b_j);
        atomicAdd(&coefS[base],      s0);
        atomicAdd(&coefS[25 + base], s1);
        atomicAdd(&coefS[50 + base], s2);
        atomicAdd(&coefS[75 + base], s3);
    }
    __syncthreads();

    // congruence transform to trig basis: C_v = T^T C_f T (exact fracs)
    if (tid < 120) {
        const float T[5][5] = {
            {0.375f,  0.5f, 0.f,   0.125f, 0.f    },
            {0.f,     0.f,  0.25f, 0.f,    0.125f },
            {0.125f,  0.f,  0.f,  -0.125f, 0.f    },
            {0.f,     0.f,  0.25f, 0.f,   -0.125f },
            {0.375f, -0.5f, 0.f,   0.125f, 0.f    }
        };
        const int q = tid / 30, r = tid % 30, al = r / 6, be = r % 6;
        float v = 0.f;
        if (be < 5) {
            #pragma unroll
            for (int a = 0; a < 5; a++) {
                float ta = T[a][al];
                if (ta != 0.f) {
                    #pragma unroll
                    for (int b = 0; b < 5; b++) {
                        float tb = T[b][be];
                        if (tb != 0.f) v += ta * tb * coefS[q * 25 + a * 5 + b];
                    }
                }
            }
        }
        g_coef_v[tid] = pk2(v, v);
    }
    __threadfence();
    __syncthreads();
    if (tid == 0) {
        asm volatile("st.release.gpu.global.b32 [%0], %1;"
                     :: "l"(&g_flag), "r"(1) : "memory");
    }
}

// Accumulate helper: compile-time al selects the v0 multiplier.
#define ACCUM(oacc, d, AL, C0v, S0v, C20v, S20v)                       \
    do {                                                               \
        if      (AL == 0) oacc = d;                                    \
        else if (AL == 1) oacc = fma2(d, C0v,  oacc);                  \
        else if (AL == 2) oacc = fma2(d, S0v,  oacc);                  \
        else if (AL == 3) oacc = fma2(d, C20v, oacc);                  \
        else              oacc = fma2(d, S20v, oacc);                  \
    } while (0)

// ---------------------------------------------------------------------------
// Single kernel. Block 0 = setup-only, exits. Blocks 1..592 = persistent
// batch, `iters` sequential tiles of 2 pairs each. ALL loop-body state is
// named scalars — no addressable local arrays (the R10 failure mode).
// ---------------------------------------------------------------------------
__global__ void __launch_bounds__(256, 4)
qnn_all(const float4* __restrict__ x, float4* __restrict__ out,
        const float* __restrict__ w, int npair, int iters)
{
    __shared__ __align__(16) u64 scp[120];
    const int tid = threadIdx.x;

    if (blockIdx.x == 0) {
        do_setup(w, tid);
        return;
    }

    const int g       = (blockIdx.x - 1) * 256 + tid;
    const int tstride = NBATCH_BLOCKS * 256;

    const u64 kTWO  = 0x4000000040000000ull;   // (2.0f, 2.0f)
    const u64 kNEG1 = 0xBF800000BF800000ull;   // (-1.0f, -1.0f)

    // -------- acquire coefficients (fast path: flag already set) --------
    if (tid == 0) {
        int f;
        asm volatile("ld.acquire.gpu.global.b32 %0, [%1];"
                     : "=r"(f) : "l"(&g_flag) : "memory");
        while (!f) {
            __nanosleep(256);
            asm volatile("ld.acquire.gpu.global.b32 %0, [%1];"
                         : "=r"(f) : "l"(&g_flag) : "memory");
        }
    }
    __syncthreads();
    if (tid < 120) scp[tid] = g_coef_v[tid];
    __syncthreads();

    #pragma unroll 1
    for (int it = 0; it < iters; it++) {
        const int piA = g + it * (2 * tstride);
        const int piB = piA + tstride;

        // -------- prelude (pair A = lanes .x, pair B = lanes .y of x2) ----
        float4 xvA = (piA < npair) ? x[piA] : make_float4(0.f, 0.f, 0.f, 0.f);
        float4 xvB = (piB < npair) ? x[piB] : make_float4(0.f, 0.f, 0.f, 0.f);

        float c0a, s0a, c1a, s1a, c0b, s0b, c1b, s1b;
        __sincosf(xvA.x, &s0a, &c0a);
        __sincosf(xvA.y, &s1a, &c1a);
        __sincosf(xvA.z, &s0b, &c0b);
        __sincosf(xvA.w, &s1b, &c1b);
        u64 C0A = pk2(c0a, c0b), S0A = pk2(s0a, s0b);
        u64 C1A = pk2(c1a, c1b), S1A = pk2(s1a, s1b);

        __sincosf(xvB.x, &s0a, &c0a);
        __sincosf(xvB.y, &s1a, &c1a);
        __sincosf(xvB.z, &s0b, &c0b);
        __sincosf(xvB.w, &s1b, &c1b);
        u64 C0B = pk2(c0a, c0b), S0B = pk2(s0a, s0b);
        u64 C1B = pk2(c1a, c1b), S1B = pk2(s1a, s1b);

        u64 C20A = fma2(mul2(C0A, C0A), kTWO, kNEG1);
        u64 S20A = mul2(mul2(C0A, S0A), kTWO);
        u64 C21A = fma2(mul2(C1A, C1A), kTWO, kNEG1);
        u64 S21A = mul2(mul2(C1A, S1A), kTWO);
        u64 C20B = fma2(mul2(C0B, C0B), kTWO, kNEG1);
        u64 S20B = mul2(mul2(C0B, S0B), kTWO);
        u64 C21B = fma2(mul2(C1B, C1B), kTWO, kNEG1);
        u64 S21B = mul2(mul2(C1B, S1B), kTWO);

        // -------- bilinear forms: named scalar accumulators only ----------
        u64 o0A, o1A, o2A, o3A, o0B, o1B, o2B, o3B;
        #pragma unroll
        for (int q = 0; q < 4; q++) {
            #pragma unroll
            for (int al = 0; al < 5; al++) {
                const u64* row = &scp[q * 30 + al * 6];
                const ulonglong2 p01 = *(const ulonglong2*)(row);
                const ulonglong2 p23 = *(const ulonglong2*)(row + 2);
                const u64 r4 = row[4];

                u64 dA = fma2(p01.y, C1A, p01.x);
                dA = fma2(p23.x, S1A, dA);
                dA = fma2(p23.y, C21A, dA);
                dA = fma2(r4,    S21A, dA);
                u64 dB = fma2(p01.y, C1B, p01.x);
                dB = fma2(p23.x, S1B, dB);
                dB = fma2(p23.y, C21B, dB);
                dB = fma2(r4,    S21B, dB);

                if (q == 0) {
                    ACCUM(o0A, dA, al, C0A, S0A, C20A, S20A);
                    ACCUM(o0B, dB, al, C0B, S0B, C20B, S20B);
                } else if (q == 1) {
                    ACCUM(o1A, dA, al, C0A, S0A, C20A, S20A);
                    ACCUM(o1B, dB, al, C0B, S0B, C20B, S20B);
                } else if (q == 2) {
                    ACCUM(o2A, dA, al, C0A, S0A, C20A, S20A);
                    ACCUM(o2B, dB, al, C0B, S0B, C20B, S20B);
                } else {
                    ACCUM(o3A, dA, al, C0A, S0A, C20A, S20A);
                    ACCUM(o3B, dB, al, C0B, S0B, C20B, S20B);
                }
            }
        }

        // -------- stores --------
        if (piA < npair) {
            float a0, b0, a1, b1, a2, b2, a3, b3;
            unpk2(o0A, a0, b0);
            unpk2(o1A, a1, b1);
            unpk2(o2A, a2, b2);
            unpk2(o3A, a3, b3);
            out[2 * piA]     = make_float4(a0, a1, a2, a3);
            out[2 * piA + 1] = make_float4(b0, b1, b2, b3);
        }
        if (piB < npair) {
            float a0, b0, a1, b1, a2, b2, a3, b3;
            unpk2(o0B, a0, b0);
            unpk2(o1B, a1, b1);
            unpk2(o2B, a2, b2);
            unpk2(o3B, a3, b3);
            out[2 * piB]     = make_float4(a0, a1, a2, a3);
            out[2 * piB + 1] = make_float4(b0, b1, b2, b3);
        }
    }
}

extern "C" void kernel_launch(void* const* d_in, const int* in_sizes, int n_in,
                              void* d_out, int out_size) {
    const float* x = (const float*)d_in[0];   // (B, 2)
    const float* w = (const float*)d_in[1];   // (3, 4, 3)
    const int n     = in_sizes[0] / 2;
    const int npair = n / 2;

    const int per_iter = NBATCH_BLOCKS * 256 * 2;   // pairs per iteration
    const int iters    = (npair + per_iter - 1) / per_iter;
    qnn_all<<<NBATCH_BLOCKS + 1, 256>>>((const float4*)x, (float4*)d_out, w,
                                        npair, iters);
}

// round 12
// speedup vs baseline: 3.6773x; 3.6773x over previous
#include <cuda_runtime.h>
#include <cuda_bf16.h>

typedef unsigned long long u64;
__device__ __forceinline__ u64 pk2(float lo, float hi) {
    u64 r; asm("mov.b64 %0, {%1, %2};" : "=l"(r) : "f"(lo), "f"(hi)); return r;
}
__device__ __forceinline__ void unpk2(u64 v, float& lo, float& hi) {
    asm("mov.b64 {%0, %1}, %2;" : "=f"(lo), "=f"(hi) : "l"(v));
}
__device__ __forceinline__ u64 mul2(u64 a, u64 b) {
    u64 r; asm("mul.rn.f32x2 %0, %1, %2;" : "=l"(r) : "l"(a), "l"(b)); return r;
}
__device__ __forceinline__ u64 add2(u64 a, u64 b) {
    u64 r; asm("add.rn.f32x2 %0, %1, %2;" : "=l"(r) : "l"(a), "l"(b)); return r;
}
__device__ __forceinline__ u64 fma2(u64 a, u64 b, u64 c) {
    u64 r; asm("fma.rn.f32x2 %0, %1, %2, %3;" : "=l"(r) : "l"(a), "l"(b), "l"(c)); return r;
}

// Coefficients in trig basis v = (1, cos x, sin x, cos 2x, sin 2x),
// packed u64 (both f32 lanes), rows padded to 6: layout [q][alpha][6].
__device__ u64 g_coef_v[120];
__device__ int g_flag = 0;

// ---------------------------------------------------------------------------
// Setup path (block 0 only), isolated via noinline. Identical to R8.
// ---------------------------------------------------------------------------
__device__ __noinline__ void do_setup(const float* __restrict__ w, int tid) {
    __shared__ float2 wcs[36];
    __shared__ float2 S[16][16];
    __shared__ float  coefS[100];

    if (tid < 36) {
        float s, c; __sincosf(0.5f * w[tid], &s, &c);
        wcs[tid] = make_float2(c, s);
    }
    if (tid >= 64 && tid < 164) coefS[tid - 64] = 0.f;
    __syncthreads();

    // 16-lane group = one column of the 16x16 unitary
    {
        const int col = tid >> 4, k = tid & 15;
        float ar = (k == col) ? 1.f : 0.f, ai = 0.f;

        int sidx = k;                 // CNOT-ring inverse permutation
        if (sidx & 1) sidx ^= 8;
        if (sidx & 2) sidx ^= 1;
        if (sidx & 4) sidx ^= 2;
        if (sidx & 8) sidx ^= 4;

        #pragma unroll
        for (int l = 0; l < 3; l++) {
            #pragma unroll
            for (int q = 0; q < 4; q++) {
                const int pos = 3 - q, mask = 1 << pos;
                const int bit = (k >> pos) & 1;
                #pragma unroll
                for (int g = 0; g < 3; g++) {
                    const float2 cs = wcs[(l * 4 + q) * 3 + g];
                    const float c = cs.x, s = cs.y;
                    float nr, ni;
                    if (g == 2) {           // RZ
                        float t = bit ? -s : s;
                        nr = c * ar + t * ai;
                        ni = c * ai - t * ar;
                    } else {
                        float pr = __shfl_xor_sync(0xffffffffu, ar, mask);
                        float pi = __shfl_xor_sync(0xffffffffu, ai, mask);
                        if (g == 0) {       // RX
                            nr = c * ar + s * pi;
                            ni = c * ai - s * pr;
                        } else {            // RY
                            float t = bit ? s : -s;
                            nr = c * ar + t * pr;
                            ni = c * ai + t * pi;
                        }
                    }
                    ar = nr; ai = ni;
                }
            }
            ar = __shfl_sync(0xffffffffu, ar, sidx, 16);
            ai = __shfl_sync(0xffffffffu, ai, sidx, 16);
        }
        S[col][k] = make_float2(ar, ai);
    }
    __syncthreads();

    // A_q collapse -> 100 monomial coefficients (shared atomics)
    {
        const int i = tid >> 4, j = tid & 15;
        float s0 = 0.f, s1 = 0.f, s2 = 0.f, s3 = 0.f;
        #pragma unroll
        for (int k = 0; k < 16; k++) {
            float2 u = S[i][k], v = S[j][k];
            float p = u.x * v.x + u.y * v.y;
            s0 += ((k >> 3) & 1) ? -p : p;
            s1 += ((k >> 2) & 1) ? -p : p;
            s2 += ((k >> 1) & 1) ? -p : p;
            s3 += ( k       & 1) ? -p : p;
        }
        const int a_i = ((i >> 3) & 1) + ((i >> 1) & 1);
        const int b_i = ((i >> 2) & 1) + (i & 1);
        const int a_j = ((j >> 3) & 1) + ((j >> 1) & 1);
        const int b_j = ((j >> 2) & 1) + (j & 1);
        const int base = (a_i + a_j) * 5 + (b_i + b_j);
        atomicAdd(&coefS[base],      s0);
        atomicAdd(&coefS[25 + base], s1);
        atomicAdd(&coefS[50 + base], s2);
        atomicAdd(&coefS[75 + base], s3);
    }
    __syncthreads();

    // congruence transform to trig basis: C_v = T^T C_f T (exact fracs)
    if (tid < 120) {
        const float T[5][5] = {
            {0.375f,  0.5f, 0.f,   0.125f, 0.f    },
            {0.f,     0.f,  0.25f, 0.f,    0.125f },
            {0.125f,  0.f,  0.f,  -0.125f, 0.f    },
            {0.f,     0.f,  0.25f, 0.f,   -0.125f },
            {0.375f, -0.5f, 0.f,   0.125f, 0.f    }
        };
        const int q = tid / 30, r = tid % 30, al = r / 6, be = r % 6;
        float v = 0.f;
        if (be < 5) {
            #pragma unroll
            for (int a = 0; a < 5; a++) {
                float ta = T[a][al];
                if (ta != 0.f) {
                    #pragma unroll
                    for (int b = 0; b < 5; b++) {
                        float tb = T[b][be];
                        if (tb != 0.f) v += ta * tb * coefS[q * 25 + a * 5 + b];
                    }
                }
            }
        }
        g_coef_v[tid] = pk2(v, v);
    }
    __threadfence();
    __syncthreads();
    if (tid == 0) {
        asm volatile("st.release.gpu.global.b32 [%0], %1;"
                     :: "l"(&g_flag), "r"(1) : "memory");
    }
}

// ---------------------------------------------------------------------------
// Single kernel, R8 straight-line shape. Block 0 = setup-only, exits.
// Blocks 1..N = batch: ONE sample-pair (2 samples) per thread, f32x2 packed.
// Low register state (8 trig + 4 acc u64) -> 5 blocks/SM without spilling.
// Tree-structured dots to shorten dependency chains.
// ---------------------------------------------------------------------------
__global__ void __launch_bounds__(256, 5)
qnn_all(const float4* __restrict__ x, float4* __restrict__ out,
        const float* __restrict__ w, int npair)
{
    __shared__ __align__(16) u64 scp[120];
    const int tid = threadIdx.x;

    if (blockIdx.x == 0) {
        do_setup(w, tid);
        return;
    }

    const int idx = (blockIdx.x - 1) * 256 + tid;

    const u64 kTWO  = 0x4000000040000000ull;   // (2.0f, 2.0f)
    const u64 kNEG1 = 0xBF800000BF800000ull;   // (-1.0f, -1.0f)

    // -------- prelude: independent of coefficients --------
    float4 xv = (idx < npair) ? x[idx] : make_float4(0.f, 0.f, 0.f, 0.f);
    float c0a, s0a, c1a, s1a, c0b, s0b, c1b, s1b;
    __sincosf(xv.x, &s0a, &c0a);
    __sincosf(xv.y, &s1a, &c1a);
    __sincosf(xv.z, &s0b, &c0b);
    __sincosf(xv.w, &s1b, &c1b);
    const u64 C0 = pk2(c0a, c0b), S0 = pk2(s0a, s0b);
    const u64 C1 = pk2(c1a, c1b), S1 = pk2(s1a, s1b);
    const u64 C20 = fma2(mul2(C0, C0), kTWO, kNEG1);
    const u64 S20 = mul2(mul2(C0, S0), kTWO);
    const u64 C21 = fma2(mul2(C1, C1), kTWO, kNEG1);
    const u64 S21 = mul2(mul2(C1, S1), kTWO);

    // -------- acquire coefficients (fast path: flag already set) --------
    if (tid == 0) {
        int f;
        asm volatile("ld.acquire.gpu.global.b32 %0, [%1];"
                     : "=r"(f) : "l"(&g_flag) : "memory");
        while (!f) {
            __nanosleep(256);
            asm volatile("ld.acquire.gpu.global.b32 %0, [%1];"
                         : "=r"(f) : "l"(&g_flag) : "memory");
        }
    }
    __syncthreads();
    if (tid < 120) scp[tid] = g_coef_v[tid];
    __syncthreads();

    // -------- bilinear forms, tree-structured --------
    u64 o0, o1, o2, o3;
    #pragma unroll
    for (int q = 0; q < 4; q++) {
        // inner dots d[al] = row . (1, C1, S1, C21, S21), depth-3 trees
        u64 d0, d1, d2, d3, d4;
        #pragma unroll
        for (int al = 0; al < 5; al++) {
            const u64* row = &scp[q * 30 + al * 6];
            const ulonglong2 p01 = *(const ulonglong2*)(row);
            const ulonglong2 p23 = *(const ulonglong2*)(row + 2);
            const u64 r4 = row[4];
            u64 ta = fma2(p01.y, C1, p01.x);          // r0 + r1*C1
            u64 tb = fma2(p23.y, C21, mul2(p23.x, S1)); // r2*S1 + r3*C21
            u64 d  = add2(fma2(r4, S21, ta), tb);
            if      (al == 0) d0 = d;
            else if (al == 1) d1 = d;
            else if (al == 2) d2 = d;
            else if (al == 3) d3 = d;
            else              d4 = d;
        }
        // outer: o = d0 + d1*C0 + d2*S0 + d3*C20 + d4*S20, depth-3 tree
        u64 t1 = fma2(d1, C0, d0);
        u64 t2 = fma2(d3, C20, mul2(d2, S0));
        u64 o  = add2(fma2(d4, S20, t1), t2);
        if      (q == 0) o0 = o;
        else if (q == 1) o1 = o;
        else if (q == 2) o2 = o;
        else             o3 = o;
    }

    if (idx < npair) {
        float a0, b0, a1, b1, a2, b2, a3, b3;
        unpk2(o0, a0, b0);
        unpk2(o1, a1, b1);
        unpk2(o2, a2, b2);
        unpk2(o3, a3, b3);
        out[2 * idx]     = make_float4(a0, a1, a2, a3);
        out[2 * idx + 1] = make_float4(b0, b1, b2, b3);
    }
}

extern "C" void kernel_launch(void* const* d_in, const int* in_sizes, int n_in,
                              void* d_out, int out_size) {
    const float* x = (const float*)d_in[0];   // (B, 2)
    const float* w = (const float*)d_in[1];   // (3, 4, 3)
    const int n     = in_sizes[0] / 2;
    const int npair = n / 2;

    const int blocks = (npair + 255) / 256 + 1;   // +1 setup block
    qnn_all<<<blocks, 256>>>((const float4*)x, (float4*)d_out, w, npair);
}

// round 13
// speedup vs baseline: 4.3409x; 1.1805x over previous
#include <cuda_runtime.h>
#include <cuda_bf16.h>

typedef unsigned long long u64;
__device__ __forceinline__ u64 pk2(float lo, float hi) {
    u64 r; asm("mov.b64 %0, {%1, %2};" : "=l"(r) : "f"(lo), "f"(hi)); return r;
}
__device__ __forceinline__ void unpk2(u64 v, float& lo, float& hi) {
    asm("mov.b64 {%0, %1}, %2;" : "=f"(lo), "=f"(hi) : "l"(v));
}
__device__ __forceinline__ u64 mul2(u64 a, u64 b) {
    u64 r; asm("mul.rn.f32x2 %0, %1, %2;" : "=l"(r) : "l"(a), "l"(b)); return r;
}
__device__ __forceinline__ u64 add2(u64 a, u64 b) {
    u64 r; asm("add.rn.f32x2 %0, %1, %2;" : "=l"(r) : "l"(a), "l"(b)); return r;
}
__device__ __forceinline__ u64 fma2(u64 a, u64 b, u64 c) {
    u64 r; asm("fma.rn.f32x2 %0, %1, %2, %3;" : "=l"(r) : "l"(a), "l"(b), "l"(c)); return r;
}

// Coefficients in trig basis v = (1, cos x, sin x, cos 2x, sin 2x),
// packed u64 (both f32 lanes), rows padded to 6: layout [q][alpha][6].
__device__ u64 g_coef_v[120];
__device__ int g_flag = 0;

#define PAIRS 2

// ---------------------------------------------------------------------------
// Setup path (block 0 only), isolated via noinline. Identical to R8.
// ---------------------------------------------------------------------------
__device__ __noinline__ void do_setup(const float* __restrict__ w, int tid) {
    __shared__ float2 wcs[36];
    __shared__ float2 S[16][16];
    __shared__ float  coefS[100];

    if (tid < 36) {
        float s, c; __sincosf(0.5f * w[tid], &s, &c);
        wcs[tid] = make_float2(c, s);
    }
    if (tid >= 64 && tid < 164) coefS[tid - 64] = 0.f;
    __syncthreads();

    // 16-lane group = one column of the 16x16 unitary
    {
        const int col = tid >> 4, k = tid & 15;
        float ar = (k == col) ? 1.f : 0.f, ai = 0.f;

        int sidx = k;                 // CNOT-ring inverse permutation
        if (sidx & 1) sidx ^= 8;
        if (sidx & 2) sidx ^= 1;
        if (sidx & 4) sidx ^= 2;
        if (sidx & 8) sidx ^= 4;

        #pragma unroll
        for (int l = 0; l < 3; l++) {
            #pragma unroll
            for (int q = 0; q < 4; q++) {
                const int pos = 3 - q, mask = 1 << pos;
                const int bit = (k >> pos) & 1;
                #pragma unroll
                for (int g = 0; g < 3; g++) {
                    const float2 cs = wcs[(l * 4 + q) * 3 + g];
                    const float c = cs.x, s = cs.y;
                    float nr, ni;
                    if (g == 2) {           // RZ
                        float t = bit ? -s : s;
                        nr = c * ar + t * ai;
                        ni = c * ai - t * ar;
                    } else {
                        float pr = __shfl_xor_sync(0xffffffffu, ar, mask);
                        float pi = __shfl_xor_sync(0xffffffffu, ai, mask);
                        if (g == 0) {       // RX
                            nr = c * ar + s * pi;
                            ni = c * ai - s * pr;
                        } else {            // RY
                            float t = bit ? s : -s;
                            nr = c * ar + t * pr;
                            ni = c * ai + t * pi;
                        }
                    }
                    ar = nr; ai = ni;
                }
            }
            ar = __shfl_sync(0xffffffffu, ar, sidx, 16);
            ai = __shfl_sync(0xffffffffu, ai, sidx, 16);
        }
        S[col][k] = make_float2(ar, ai);
    }
    __syncthreads();

    // A_q collapse -> 100 monomial coefficients (shared atomics)
    {
        const int i = tid >> 4, j = tid & 15;
        float s0 = 0.f, s1 = 0.f, s2 = 0.f, s3 = 0.f;
        #pragma unroll
        for (int k = 0; k < 16; k++) {
            float2 u = S[i][k], v = S[j][k];
            float p = u.x * v.x + u.y * v.y;
            s0 += ((k >> 3) & 1) ? -p : p;
            s1 += ((k >> 2) & 1) ? -p : p;
            s2 += ((k >> 1) & 1) ? -p : p;
            s3 += ( k       & 1) ? -p : p;
        }
        const int a_i = ((i >> 3) & 1) + ((i >> 1) & 1);
        const int b_i = ((i >> 2) & 1) + (i & 1);
        const int a_j = ((j >> 3) & 1) + ((j >> 1) & 1);
        const int b_j = ((j >> 2) & 1) + (j & 1);
        const int base = (a_i + a_j) * 5 + (b_i + b_j);
        atomicAdd(&coefS[base],      s0);
        atomicAdd(&coefS[25 + base], s1);
        atomicAdd(&coefS[50 + base], s2);
        atomicAdd(&coefS[75 + base], s3);
    }
    __syncthreads();

    // congruence transform to trig basis: C_v = T^T C_f T (exact fracs)
    if (tid < 120) {
        const float T[5][5] = {
            {0.375f,  0.5f, 0.f,   0.125f, 0.f    },
            {0.f,     0.f,  0.25f, 0.f,    0.125f },
            {0.125f,  0.f,  0.f,  -0.125f, 0.f    },
            {0.f,     0.f,  0.25f, 0.f,   -0.125f },
            {0.375f, -0.5f, 0.f,   0.125f, 0.f    }
        };
        const int q = tid / 30, r = tid % 30, al = r / 6, be = r % 6;
        float v = 0.f;
        if (be < 5) {
            #pragma unroll
            for (int a = 0; a < 5; a++) {
                float ta = T[a][al];
                if (ta != 0.f) {
                    #pragma unroll
                    for (int b = 0; b < 5; b++) {
                        float tb = T[b][be];
                        if (tb != 0.f) v += ta * tb * coefS[q * 25 + a * 5 + b];
                    }
                }
            }
        }
        g_coef_v[tid] = pk2(v, v);
    }
    __threadfence();
    __syncthreads();
    if (tid == 0) {
        asm volatile("st.release.gpu.global.b32 [%0], %1;"
                     :: "l"(&g_flag), "r"(1) : "memory");
    }
}

// ---------------------------------------------------------------------------
// Single kernel, R8 shape. Block 0 = setup-only, exits. Blocks 1..N = batch:
// 2 pairs (4 samples) per thread, f32x2 packed, straight-line, TREE dots.
// ---------------------------------------------------------------------------
__global__ void __launch_bounds__(256, 4)
qnn_all(const float4* __restrict__ x, float4* __restrict__ out,
        const float* __restrict__ w, int npair)
{
    __shared__ __align__(16) u64 scp[120];
    const int tid = threadIdx.x;

    if (blockIdx.x == 0) {
        do_setup(w, tid);
        return;
    }

    const int t0      = (blockIdx.x - 1) * 256 + tid;
    const int tstride = (gridDim.x - 1) * 256;

    const u64 kTWO  = 0x4000000040000000ull;   // (2.0f, 2.0f)
    const u64 kNEG1 = 0xBF800000BF800000ull;   // (-1.0f, -1.0f)

    // -------- prelude: independent of coefficients --------
    u64 C0[PAIRS], S0[PAIRS], C20[PAIRS], S20[PAIRS];
    u64 C1[PAIRS], S1[PAIRS], C21[PAIRS], S21[PAIRS];
    #pragma unroll
    for (int p = 0; p < PAIRS; p++) {
        const int pi_ = t0 + p * tstride;
        float4 xv = (pi_ < npair) ? x[pi_] : make_float4(0.f, 0.f, 0.f, 0.f);
        float c0a, s0a, c1a, s1a, c0b, s0b, c1b, s1b;
        __sincosf(xv.x, &s0a, &c0a);
        __sincosf(xv.y, &s1a, &c1a);
        __sincosf(xv.z, &s0b, &c0b);
        __sincosf(xv.w, &s1b, &c1b);
        C0[p] = pk2(c0a, c0b); S0[p] = pk2(s0a, s0b);
        C1[p] = pk2(c1a, c1b); S1[p] = pk2(s1a, s1b);
        C20[p] = fma2(mul2(C0[p], C0[p]), kTWO, kNEG1);
        S20[p] = mul2(mul2(C0[p], S0[p]), kTWO);
        C21[p] = fma2(mul2(C1[p], C1[p]), kTWO, kNEG1);
        S21[p] = mul2(mul2(C1[p], S1[p]), kTWO);
    }

    // -------- acquire coefficients (fast path: flag already set) --------
    if (tid == 0) {
        int f;
        asm volatile("ld.acquire.gpu.global.b32 %0, [%1];"
                     : "=r"(f) : "l"(&g_flag) : "memory");
        while (!f) {
            __nanosleep(256);
            asm volatile("ld.acquire.gpu.global.b32 %0, [%1];"
                         : "=r"(f) : "l"(&g_flag) : "memory");
        }
    }
    __syncthreads();
    if (tid < 120) scp[tid] = g_coef_v[tid];
    __syncthreads();

    // -------- bilinear forms: tree dots, coefficients shared across pairs ---
    u64 o0[PAIRS], o1[PAIRS], o2[PAIRS], o3[PAIRS];
    #pragma unroll
    for (int q = 0; q < 4; q++) {
        // accumulate with two parallel chains per pair, merged at the end
        u64 eA = 0ull, fA = 0ull, eB = 0ull, fB = 0ull;   // chain pairs
        #pragma unroll
        for (int al = 0; al < 5; al++) {
            const u64* row = &scp[q * 30 + al * 6];
            const ulonglong2 p01 = *(const ulonglong2*)(row);
            const ulonglong2 p23 = *(const ulonglong2*)(row + 2);
            const u64 r4 = row[4];
            #pragma unroll
            for (int p = 0; p < PAIRS; p++) {
                // inner dot, two chains depth<=3:
                //   ta = r0 + r1*C1
                //   tb = (r2*S1 + r3*C21) + r4*S21
                u64 ta = fma2(p01.y, C1[p], p01.x);
                u64 tb = fma2(p23.y, C21[p], mul2(p23.x, S1[p]));
                tb = fma2(r4, S21[p], tb);
                u64 d = add2(ta, tb);
                // outer: alternate accumulation across two chains (e,f)
                u64 v0 = (al == 1) ? C0[p] : (al == 2) ? S0[p]
                       : (al == 3) ? C20[p] : S20[p];
                if (p == 0) {
                    if (al == 0)            eA = d;
                    else if (al & 1)        eA = fma2(d, v0, eA);   // al=1,3
                    else                    fA = fma2(d, v0, fA);   // al=2,4
                } else {
                    if (al == 0)            eB = d;
                    else if (al & 1)        eB = fma2(d, v0, eB);
                    else                    fB = fma2(d, v0, fB);
                }
            }
        }
        u64 oA = add2(eA, fA);
        u64 oB = add2(eB, fB);
        if      (q == 0) { o0[0] = oA; o0[1] = oB; }
        else if (q == 1) { o1[0] = oA; o1[1] = oB; }
        else if (q == 2) { o2[0] = oA; o2[1] = oB; }
        else             { o3[0] = oA; o3[1] = oB; }
    }

    #pragma unroll
    for (int p = 0; p < PAIRS; p++) {
        const int pi_ = t0 + p * tstride;
        if (pi_ < npair) {
            float a0, b0, a1, b1, a2, b2, a3, b3;
            unpk2(o0[p], a0, b0);
            unpk2(o1[p], a1, b1);
            unpk2(o2[p], a2, b2);
            unpk2(o3[p], a3, b3);
            out[2 * pi_]     = make_float4(a0, a1, a2, a3);
            out[2 * pi_ + 1] = make_float4(b0, b1, b2, b3);
        }
    }
}

extern "C" void kernel_launch(void* const* d_in, const int* in_sizes, int n_in,
                              void* d_out, int out_size) {
    const float* x = (const float*)d_in[0];   // (B, 2)
    const float* w = (const float*)d_in[1];   // (3, 4, 3)
    const int n     = in_sizes[0] / 2;
    const int npair = n / 2;

    const int blocks = (npair / PAIRS + 255) / 256 + 1;   // +1 setup block
    qnn_all<<<blocks, 256>>>((const float4*)x, (float4*)d_out, w, npair);
}